// round 1
// baseline (speedup 1.0000x reference)
#include <cuda_runtime.h>
#include <math.h>

#define NSC 128
#define NVC 64
#define TPCC 192
#define NNODES 16000
#define NEDGES 256000

#define INV_SQRT_NS 0.08838834764831845f
#define INV_SQRT_NV 0.125f
#define INV_SQRT_TPC 0.07216878364870323f
#define INV_SQRT3 0.5773502691896258f

// ---------------- scratch (static device globals; no runtime allocs) --------
__device__ float g_xs[NNODES * NSC];            // [n][128]
__device__ float g_xv[NNODES * 3 * NVC];        // [n][c][64]
__device__ float g_h[NEDGES * 128];             // [e][128]
__device__ float g_w[NEDGES * 384];             // [e][384]
__device__ float g_accs[NNODES * TPCC];         // [n][192]
__device__ float g_accv[NNODES * 3 * TPCC];     // [n][c][192]

// ---------------- helpers ----------------------------------------------------
__device__ __forceinline__ float silu_f(float x) {
    return x / (1.0f + __expf(-x));
}

__device__ __forceinline__ float4 f4mul(float4 a, float4 b) {
    return make_float4(a.x * b.x, a.y * b.y, a.z * b.z, a.w * b.w);
}
__device__ __forceinline__ float4 f4scale(float4 a, float s) {
    return make_float4(a.x * s, a.y * s, a.z * s, a.w * s);
}
__device__ __forceinline__ float4 f4fmas(float4 a, float s, float4 c) {
    return make_float4(fmaf(a.x, s, c.x), fmaf(a.y, s, c.y),
                       fmaf(a.z, s, c.z), fmaf(a.w, s, c.w));
}

// vectorized global float4 reduction (red.global.add.v4.f32, PTX ISA 8.1+, sm_90+)
__device__ __forceinline__ void red4(float* p, float4 v) {
    asm volatile("red.global.add.v4.f32 [%0], {%1, %2, %3, %4};"
                 :: "l"(p), "f"(v.x), "f"(v.y), "f"(v.z), "f"(v.w)
                 : "memory");
}

// ---------------- K1: node pre-mix ------------------------------------------
// 8 nodes / block; threads 0..127 -> x_s columns, 128..319 -> (c, v') of x_v.
__global__ __launch_bounds__(320) void k_node_pre(
    const float* __restrict__ nf, const float* __restrict__ Ws,
    const float* __restrict__ bs, const float* __restrict__ Wv)
{
    __shared__ float sv[8][320];
    const int n0 = blockIdx.x * 8;
    const int tid = threadIdx.x;

    for (int idx = tid; idx < 8 * 320; idx += 320) {
        sv[idx / 320][idx % 320] = nf[(n0 + idx / 320) * 320 + idx % 320];
    }
    __syncthreads();

    if (tid < 128) {
        const int j = tid;
        float acc[8];
#pragma unroll
        for (int i = 0; i < 8; i++) acc[i] = 0.0f;
        for (int u = 0; u < 128; u++) {
            const float w = Ws[u * 128 + j];
#pragma unroll
            for (int i = 0; i < 8; i++) acc[i] = fmaf(sv[i][u], w, acc[i]);
        }
        const float b = bs[j];
#pragma unroll
        for (int i = 0; i < 8; i++)
            g_xs[(n0 + i) * 128 + j] = fmaf(acc[i], INV_SQRT_NS, b);
    } else {
        const int t = tid - 128;
        const int c = t / 64, vp = t % 64;
        float acc[8];
#pragma unroll
        for (int i = 0; i < 8; i++) acc[i] = 0.0f;
        for (int u = 0; u < 64; u++) {
            const float w = Wv[u * 64 + vp];
#pragma unroll
            for (int i = 0; i < 8; i++)
                acc[i] = fmaf(sv[i][128 + 3 * u + c], w, acc[i]);
        }
#pragma unroll
        for (int i = 0; i < 8; i++)
            g_xv[(n0 + i) * 192 + c * 64 + vp] = acc[i] * INV_SQRT_NV;
    }
}

// ---------------- K2: edge MLP layer 1  h = silu(ea @ W1 + b1) ---------------
// 8 edges / block of 256 threads; thread -> (edge, 4 output cols).
__global__ __launch_bounds__(256) void k_edge_mlp1(
    const float* __restrict__ ea, const float* __restrict__ W1,
    const float* __restrict__ b1)
{
    __shared__ float W1s[16 * 128];
    __shared__ float b1s[128];
    __shared__ float eas[8][16];
    const int tid = threadIdx.x;
    const int e0 = blockIdx.x * 8;

    for (int idx = tid; idx < 2048; idx += 256) W1s[idx] = W1[idx];
    if (tid < 128) {
        b1s[tid] = b1[tid];
        eas[tid / 16][tid % 16] = ea[e0 * 16 + tid];
    }
    __syncthreads();

    const int i = tid >> 5;            // local edge 0..7
    const int q = (tid & 31) * 4;      // column base 0..124
    float4 acc = *(const float4*)(b1s + q);
#pragma unroll
    for (int k = 0; k < 16; k++) {
        const float a = eas[i][k];
        const float4 w = *(const float4*)(W1s + k * 128 + q);
        acc = f4fmas(w, a, acc);
    }
    acc.x = silu_f(acc.x);
    acc.y = silu_f(acc.y);
    acc.z = silu_f(acc.z);
    acc.w = silu_f(acc.w);
    *(float4*)(g_h + (e0 + i) * 128 + q) = acc;
}

// ---------------- K3: edge MLP layer 2  w = h @ W2 + b2 ----------------------
// M=256000, N=384, K=128. BM=BN=128, BK=16, 256 threads, 8x8 register tiles.
__global__ __launch_bounds__(256, 2) void k_edge_mlp2(
    const float* __restrict__ W2, const float* __restrict__ b2)
{
    __shared__ float As[16][128];   // [k][m]
    __shared__ float Bs[16][128];   // [k][n]
    const int m0 = blockIdx.y * 128;
    const int n0 = blockIdx.x * 128;
    const int tid = threadIdx.x;
    const int tx = tid & 15;        // n-tile
    const int ty = tid >> 4;        // m-tile
    const int arow = tid >> 1;
    const int akq = (tid & 1) * 8;
    const int bk = tid >> 4;
    const int bn = (tid & 15) * 8;

    float acc[8][8];
#pragma unroll
    for (int i = 0; i < 8; i++)
#pragma unroll
        for (int j = 0; j < 8; j++) acc[i][j] = 0.0f;

    // preload tile 0 into registers
    float4 a0 = *(const float4*)(g_h + (m0 + arow) * 128 + akq);
    float4 a1 = *(const float4*)(g_h + (m0 + arow) * 128 + akq + 4);
    float4 b0v = *(const float4*)(W2 + bk * 384 + n0 + bn);
    float4 b1v = *(const float4*)(W2 + bk * 384 + n0 + bn + 4);

    for (int kt = 0; kt < 8; kt++) {
        // stage registers -> smem
        As[akq + 0][arow] = a0.x; As[akq + 1][arow] = a0.y;
        As[akq + 2][arow] = a0.z; As[akq + 3][arow] = a0.w;
        As[akq + 4][arow] = a1.x; As[akq + 5][arow] = a1.y;
        As[akq + 6][arow] = a1.z; As[akq + 7][arow] = a1.w;
        *(float4*)(&Bs[bk][bn]) = b0v;
        *(float4*)(&Bs[bk][bn + 4]) = b1v;
        __syncthreads();

        if (kt < 7) {   // prefetch next tile while computing
            const int k0n = (kt + 1) * 16;
            a0 = *(const float4*)(g_h + (m0 + arow) * 128 + k0n + akq);
            a1 = *(const float4*)(g_h + (m0 + arow) * 128 + k0n + akq + 4);
            b0v = *(const float4*)(W2 + (k0n + bk) * 384 + n0 + bn);
            b1v = *(const float4*)(W2 + (k0n + bk) * 384 + n0 + bn + 4);
        }

#pragma unroll
        for (int k = 0; k < 16; k++) {
            float af[8], bf[8];
            *(float4*)(af) = *(const float4*)(&As[k][ty * 8]);
            *(float4*)(af + 4) = *(const float4*)(&As[k][ty * 8 + 4]);
            *(float4*)(bf) = *(const float4*)(&Bs[k][tx * 8]);
            *(float4*)(bf + 4) = *(const float4*)(&Bs[k][tx * 8 + 4]);
#pragma unroll
            for (int i = 0; i < 8; i++)
#pragma unroll
                for (int j = 0; j < 8; j++)
                    acc[i][j] = fmaf(af[i], bf[j], acc[i][j]);
        }
        __syncthreads();
    }

    const float4 bb0 = *(const float4*)(b2 + n0 + tx * 8);
    const float4 bb1 = *(const float4*)(b2 + n0 + tx * 8 + 4);
#pragma unroll
    for (int i = 0; i < 8; i++) {
        const int row = m0 + ty * 8 + i;
        float4 o0 = make_float4(acc[i][0] + bb0.x, acc[i][1] + bb0.y,
                                acc[i][2] + bb0.z, acc[i][3] + bb0.w);
        float4 o1 = make_float4(acc[i][4] + bb1.x, acc[i][5] + bb1.y,
                                acc[i][6] + bb1.z, acc[i][7] + bb1.w);
        *(float4*)(g_w + row * 384 + n0 + tx * 8) = o0;
        *(float4*)(g_w + row * 384 + n0 + tx * 8 + 4) = o1;
    }
}

// ---------------- K4: edge messages + scatter-add ----------------------------
// one warp per edge; float4 vector reductions into acc_s / acc_v.
__global__ __launch_bounds__(256) void k_scatter(
    const int* __restrict__ eidx, const float* __restrict__ rsh)
{
    const int e = blockIdx.x * 8 + (threadIdx.x >> 5);
    const int lane = threadIdx.x & 31;
    const int dst = eidx[e];
    const int src = eidx[NEDGES + e];
    const float4 r = *(const float4*)(rsh + 4 * e);   // r0 = r.x, r1 = (y,z,w)

    const float* we = g_w + e * 384;
    const float* xs = g_xs + src * 128;
    const float* xv = g_xv + src * 192;
    float* as_ = g_accs + dst * 192;
    float* av = g_accv + dst * 576;

    // channels 0..127 (scalar-derived part), one float4 group per lane
    {
        const int ch0 = lane * 4;
        const float4 wss = *(const float4*)(we + ch0);         // w_ss0
        const float4 wsv = *(const float4*)(we + 192 + ch0);   // w_sv1
        const float4 sj  = *(const float4*)(xs + ch0);
        red4(as_ + ch0, f4scale(f4mul(wss, sj), r.x));
        const float4 base = f4mul(wsv, sj);
        red4(av + ch0,        f4scale(base, r.y));
        red4(av + 192 + ch0,  f4scale(base, r.z));
        red4(av + 384 + ch0,  f4scale(base, r.w));
    }
    // channels 128..191 (vector-derived part), lanes 0..15
    if (lane < 16) {
        const int u0 = lane * 4;
        const float4 wvv = *(const float4*)(we + 128 + u0);    // w_vv0
        const float4 wvs = *(const float4*)(we + 320 + u0);    // w_vs1
        const float4 v0 = *(const float4*)(xv + u0);
        const float4 v1 = *(const float4*)(xv + 64 + u0);
        const float4 v2 = *(const float4*)(xv + 128 + u0);
        float4 vd = f4scale(v0, r.y);
        vd = f4fmas(v1, r.z, vd);
        vd = f4fmas(v2, r.w, vd);
        red4(as_ + 128 + u0, f4scale(f4mul(wvv, vd), INV_SQRT3));
        const float4 wr = f4scale(wvs, r.x);
        red4(av + 128 + u0,        f4mul(wr, v0));
        red4(av + 192 + 128 + u0,  f4mul(wr, v1));
        red4(av + 384 + 128 + u0,  f4mul(wr, v2));
    }
}

// ---------------- K5: gating + node post-mix + residual ----------------------
__global__ __launch_bounds__(320) void k_node_post(
    const float* __restrict__ Wps, const float* __restrict__ Wpv,
    const float* __restrict__ xs_unused, float* __restrict__ out)
{
    __shared__ float gs[8][192];
    __shared__ float gv[8][3][192];
    const int n0 = blockIdx.x * 8;
    const int tid = threadIdx.x;

    for (int idx = tid; idx < 8 * 192; idx += 320) {
        const int i = idx / 192, u = idx % 192;
        const float a = g_accs[(n0 + i) * 192 + u];
        gs[i][u] = silu_f(a);
        const float v0 = g_accv[(n0 + i) * 576 + u];
        const float v1 = g_accv[(n0 + i) * 576 + 192 + u];
        const float v2 = g_accv[(n0 + i) * 576 + 384 + u];
        const float nrm = sqrtf(fmaf(v0, v0, fmaf(v1, v1, fmaf(v2, v2, 1e-12f))));
        const float sg = 1.0f / (1.0f + __expf(-nrm));
        gv[i][0][u] = v0 * sg;
        gv[i][1][u] = v1 * sg;
        gv[i][2][u] = v2 * sg;
    }
    __syncthreads();

    if (tid < 128) {
        const int j = tid;
        float acc[8];
#pragma unroll
        for (int i = 0; i < 8; i++) acc[i] = 0.0f;
        for (int u = 0; u < 192; u++) {
            const float w = Wps[u * 128 + j];
#pragma unroll
            for (int i = 0; i < 8; i++) acc[i] = fmaf(gs[i][u], w, acc[i]);
        }
#pragma unroll
        for (int i = 0; i < 8; i++)
            out[(n0 + i) * 320 + j] =
                g_xs[(n0 + i) * 128 + j] + acc[i] * INV_SQRT_TPC;
    } else {
        const int t = tid - 128;
        const int c = t / 64, vp = t % 64;
        float acc[8];
#pragma unroll
        for (int i = 0; i < 8; i++) acc[i] = 0.0f;
        for (int u = 0; u < 192; u++) {
            const float w = Wpv[u * 64 + vp];
#pragma unroll
            for (int i = 0; i < 8; i++) acc[i] = fmaf(gv[i][c][u], w, acc[i]);
        }
#pragma unroll
        for (int i = 0; i < 8; i++)
            out[(n0 + i) * 320 + 128 + vp * 3 + c] =
                g_xv[(n0 + i) * 192 + c * 64 + vp] + acc[i] * INV_SQRT_TPC;
    }
}

// ---------------- launcher ---------------------------------------------------
extern "C" void kernel_launch(void* const* d_in, const int* in_sizes, int n_in,
                              void* d_out, int out_size)
{
    (void)in_sizes; (void)n_in; (void)out_size;
    const float* nf   = (const float*)d_in[0];   // node_feat (16000, 320)
    const float* ea   = (const float*)d_in[1];   // edge_attr (256000, 16)
    const float* rsh  = (const float*)d_in[2];   // edge_rshs (256000, 4)
    const int*   eidx = (const int*)d_in[3];     // edge_index (2, 256000) int32
    const float* Wps  = (const float*)d_in[4];   // W_pre_s (128,128)
    const float* bps  = (const float*)d_in[5];   // b_pre_s (128,)
    const float* Wpv  = (const float*)d_in[6];   // W_pre_v (64,64)
    const float* W1   = (const float*)d_in[7];   // W1 (16,128)
    const float* b1   = (const float*)d_in[8];   // b1 (128,)
    const float* W2   = (const float*)d_in[9];   // W2 (128,384)
    const float* b2   = (const float*)d_in[10];  // b2 (384,)
    const float* Wposts = (const float*)d_in[11]; // W_post_s (192,128)
    const float* Wpostv = (const float*)d_in[12]; // W_post_v (192,64)
    float* out = (float*)d_out;

    void* accs_ptr = nullptr;
    void* accv_ptr = nullptr;
    cudaGetSymbolAddress(&accs_ptr, g_accs);
    cudaGetSymbolAddress(&accv_ptr, g_accv);
    cudaMemsetAsync(accs_ptr, 0, sizeof(float) * NNODES * TPCC);
    cudaMemsetAsync(accv_ptr, 0, sizeof(float) * NNODES * 3 * TPCC);

    k_node_pre<<<NNODES / 8, 320>>>(nf, Wps, bps, Wpv);
    k_edge_mlp1<<<NEDGES / 8, 256>>>(ea, W1, b1);
    k_edge_mlp2<<<dim3(3, NEDGES / 128), 256>>>(W2, b2);
    k_scatter<<<NEDGES / 8, 256>>>(eidx, rsh);
    k_node_post<<<NNODES / 8, 320>>>(Wposts, Wpostv, nullptr, out);
}